// round 1
// baseline (speedup 1.0000x reference)
#include <cuda_runtime.h>

#define N_NODES 100000
#define F_IN    128
#define HDIM    64
#define CDIM    40

// ---- scratch (device globals: no allocation allowed in kernel_launch) ----
__device__ __align__(256) float g_deg [N_NODES];
__device__ __align__(256) float g_dinv[N_NODES];
__device__ __align__(256) float g_h1s [N_NODES * HDIM];   // (x@W1) * dinv[row]
__device__ __align__(256) float g_agg1[N_NODES * HDIM];   // init = h1s (self loop), += h1s[src]
__device__ __align__(256) float g_h2s [N_NODES * CDIM];
__device__ __align__(256) float g_agg2[N_NODES * CDIM];

// ---------------------------------------------------------------- degree ----
__global__ void k_init_deg() {
    int i = blockIdx.x * blockDim.x + threadIdx.x;
    if (i < N_NODES) g_deg[i] = 1.0f;   // self loop
}

__global__ void k_deg(const int* __restrict__ ei, int E) {
    int e = blockIdx.x * blockDim.x + threadIdx.x;
    if (e >= E) return;
    int d = ei[E + e];
    if ((unsigned)d < (unsigned)N_NODES) atomicAdd(&g_deg[d], 1.0f);
}

__global__ void k_dinv() {
    int i = blockIdx.x * blockDim.x + threadIdx.x;
    if (i < N_NODES) g_dinv[i] = rsqrtf(g_deg[i]);
}

// ------------------------------------------------------- GEMM1: h1s = xW1*dinv
// Block: 256 threads = 16 colgroups (x4 cols = 64) x 16 rowgroups (x8 rows = 128 rows)
__global__ __launch_bounds__(256) void k_gemm1(const float* __restrict__ x,
                                               const float* __restrict__ W1) {
    __shared__ float Ws[32 * 64];       // k-chunk x 64 cols   (8 KB)
    __shared__ float Xs[128 * 33];      // 128 rows x 32 k, pad 33 (16.9 KB)

    const int tid = threadIdx.x;
    const int cg  = tid & 15;           // col group: cols cg*4 .. cg*4+3
    const int rg  = tid >> 4;           // row group: rows rg*8 .. rg*8+7
    const int rowBase = blockIdx.x * 128;

    float4 acc[8];
    #pragma unroll
    for (int r = 0; r < 8; r++) acc[r] = make_float4(0.f, 0.f, 0.f, 0.f);

    for (int k0 = 0; k0 < F_IN; k0 += 32) {
        // stage W chunk: [32][64]
        for (int i = tid; i < 32 * 64; i += 256)
            Ws[i] = W1[(k0 + (i >> 6)) * HDIM + (i & 63)];
        // stage X chunk: [128][32] (padded)
        for (int i = tid; i < 128 * 32; i += 256) {
            int r = i >> 5, k = i & 31;
            int row = rowBase + r;
            Xs[r * 33 + k] = (row < N_NODES) ? x[(long long)row * F_IN + k0 + k] : 0.f;
        }
        __syncthreads();
        #pragma unroll
        for (int k = 0; k < 32; k++) {
            float4 w = *(const float4*)&Ws[k * 64 + cg * 4];
            #pragma unroll
            for (int r = 0; r < 8; r++) {
                float xv = Xs[(rg * 8 + r) * 33 + k];
                acc[r].x += xv * w.x; acc[r].y += xv * w.y;
                acc[r].z += xv * w.z; acc[r].w += xv * w.w;
            }
        }
        __syncthreads();
    }

    #pragma unroll
    for (int r = 0; r < 8; r++) {
        int row = rowBase + rg * 8 + r;
        if (row < N_NODES) {
            float s = g_dinv[row];
            float4 o = make_float4(acc[r].x * s, acc[r].y * s, acc[r].z * s, acc[r].w * s);
            *(float4*)&g_h1s [(long long)row * HDIM + cg * 4] = o;
            *(float4*)&g_agg1[(long long)row * HDIM + cg * 4] = o;   // self-loop init
        }
    }
}

// ------------------------------------------------ scatter1: agg1[dst] += h1s[src]
__global__ void k_scatter1(const int* __restrict__ ei, int E) {
    long long idx = (long long)blockIdx.x * blockDim.x + threadIdx.x;
    long long total = (long long)E * 16;          // 16 float4 chunks per edge
    if (idx >= total) return;
    int e = (int)(idx >> 4);
    int c = ((int)idx & 15) * 4;
    int s = ei[e], d = ei[E + e];
    if ((unsigned)s >= (unsigned)N_NODES || (unsigned)d >= (unsigned)N_NODES) return;
    float4 v = *(const float4*)&g_h1s[(long long)s * HDIM + c];
    float* p = &g_agg1[(long long)d * HDIM + c];
    asm volatile("red.global.add.v4.f32 [%0], {%1, %2, %3, %4};"
                 :: "l"(p), "f"(v.x), "f"(v.y), "f"(v.z), "f"(v.w) : "memory");
}

// --------------------------------- GEMM2: h2s = relu(dinv*agg1 + b1) @ W2 * dinv
// Block: 320 threads = 10 colgroups (x4 = 40) x 32 rowgroups (x4 rows = 128 rows)
__global__ __launch_bounds__(320) void k_gemm2(const float* __restrict__ W2,
                                               const float* __restrict__ b1) {
    __shared__ float Ws[64 * 40];        // 10.2 KB
    __shared__ float Xs[128 * 65];       // 33.3 KB (padded)
    __shared__ float Bs[64];

    const int tid = threadIdx.x;
    const int cg  = tid % 10;
    const int rg  = tid / 10;            // 0..31, rows rg*4 .. rg*4+3
    const int rowBase = blockIdx.x * 128;

    for (int i = tid; i < 64 * 40; i += 320) Ws[i] = W2[i];
    if (tid < 64) Bs[tid] = b1[tid];
    __syncthreads();   // Bs ready before Xs staging uses it

    for (int i = tid; i < 128 * 64; i += 320) {
        int r = i >> 6, k = i & 63;
        int row = rowBase + r;
        float v = 0.f;
        if (row < N_NODES)
            v = fmaxf(g_dinv[row] * g_agg1[(long long)row * HDIM + k] + Bs[k], 0.f);
        Xs[r * 65 + k] = v;
    }
    __syncthreads();

    float4 acc[4];
    #pragma unroll
    for (int r = 0; r < 4; r++) acc[r] = make_float4(0.f, 0.f, 0.f, 0.f);

    #pragma unroll 4
    for (int k = 0; k < 64; k++) {
        float4 w = *(const float4*)&Ws[k * 40 + cg * 4];
        #pragma unroll
        for (int r = 0; r < 4; r++) {
            float xv = Xs[(rg * 4 + r) * 65 + k];
            acc[r].x += xv * w.x; acc[r].y += xv * w.y;
            acc[r].z += xv * w.z; acc[r].w += xv * w.w;
        }
    }

    #pragma unroll
    for (int r = 0; r < 4; r++) {
        int row = rowBase + rg * 4 + r;
        if (row < N_NODES) {
            float s = g_dinv[row];
            float4 o = make_float4(acc[r].x * s, acc[r].y * s, acc[r].z * s, acc[r].w * s);
            *(float4*)&g_h2s [(long long)row * CDIM + cg * 4] = o;
            *(float4*)&g_agg2[(long long)row * CDIM + cg * 4] = o;   // self-loop init
        }
    }
}

// ------------------------------------------------ scatter2: agg2[dst] += h2s[src]
__global__ void k_scatter2(const int* __restrict__ ei, int E) {
    long long idx = (long long)blockIdx.x * blockDim.x + threadIdx.x;
    long long total = (long long)E * 10;          // 10 float4 chunks per edge
    if (idx >= total) return;
    int e = (int)(idx / 10);
    int c = (int)(idx % 10) * 4;
    int s = ei[e], d = ei[E + e];
    if ((unsigned)s >= (unsigned)N_NODES || (unsigned)d >= (unsigned)N_NODES) return;
    float4 v = *(const float4*)&g_h2s[(long long)s * CDIM + c];
    float* p = &g_agg2[(long long)d * CDIM + c];
    asm volatile("red.global.add.v4.f32 [%0], {%1, %2, %3, %4};"
                 :: "l"(p), "f"(v.x), "f"(v.y), "f"(v.z), "f"(v.w) : "memory");
}

// -------------------------------------- final: out = log_softmax(dinv*agg2 + b2)
// one warp per row; lanes 0..31 hold cols 0..31, lanes 0..7 also hold cols 32..39
__global__ void k_final(const float* __restrict__ b2, float* __restrict__ out) {
    int gtid = blockIdx.x * blockDim.x + threadIdx.x;
    int row  = gtid >> 5;
    int lane = threadIdx.x & 31;
    if (row >= N_NODES) return;
    const float* rp = &g_agg2[(long long)row * CDIM];
    float s  = g_dinv[row];
    float a0 = s * rp[lane] + b2[lane];
    float a1 = (lane < 8) ? (s * rp[32 + lane] + b2[32 + lane]) : -3.4e38f;
    float m  = fmaxf(a0, a1);
    #pragma unroll
    for (int o = 16; o; o >>= 1) m = fmaxf(m, __shfl_xor_sync(0xFFFFFFFFu, m, o));
    float es = expf(a0 - m) + ((lane < 8) ? expf(a1 - m) : 0.f);
    #pragma unroll
    for (int o = 16; o; o >>= 1) es += __shfl_xor_sync(0xFFFFFFFFu, es, o);
    float l = m + logf(es);
    out[(long long)row * CDIM + lane] = a0 - l;
    if (lane < 8) out[(long long)row * CDIM + 32 + lane] = a1 - l;
}

// ---------------------------------------------------------------------------
extern "C" void kernel_launch(void* const* d_in, const int* in_sizes, int n_in,
                              void* d_out, int out_size) {
    const float* x  = (const float*)d_in[0];
    const int*   ei = (const int*)  d_in[1];
    const float* W1 = (const float*)d_in[2];
    const float* b1 = (const float*)d_in[3];
    const float* W2 = (const float*)d_in[4];
    const float* b2 = (const float*)d_in[5];
    float* out = (float*)d_out;
    const int E = in_sizes[1] / 2;

    k_init_deg<<<(N_NODES + 255) / 256, 256>>>();
    k_deg<<<(E + 255) / 256, 256>>>(ei, E);
    k_dinv<<<(N_NODES + 255) / 256, 256>>>();

    k_gemm1<<<(N_NODES + 127) / 128, 256>>>(x, W1);
    {
        long long tot = (long long)E * 16;
        k_scatter1<<<(int)((tot + 255) / 256), 256>>>(ei, E);
    }
    k_gemm2<<<(N_NODES + 127) / 128, 320>>>(W2, b1);
    {
        long long tot = (long long)E * 10;
        k_scatter2<<<(int)((tot + 255) / 256), 256>>>(ei, E);
    }
    k_final<<<(N_NODES * 32 + 255) / 256, 256>>>(b2, out);
}